// round 8
// baseline (speedup 1.0000x reference)
#include <cuda_runtime.h>
#include <cuda_bf16.h>
#include <cstdint>
#include <cstddef>

#define TST 192
#define BAT 256
#define HID 512
#define G4  2048
#define RWS (TST*BAT)

__device__ __nv_bfloat16 g_X[(size_t)RWS*64];
__device__ float g_XZ[(size_t)RWS*G4];
__device__ __nv_bfloat16 g_H1[(size_t)RWS*HID];
__device__ __nv_bfloat16 g_H2[(size_t)RWS*HID];
__device__ unsigned g_Hb[2][32*BAT*8];   // packed bf16 h ping-pong [kb16][b][8 u32]
__device__ unsigned g_Wk1p[32*G4];
__device__ unsigned g_Wk2r[256*G4];
__device__ volatile unsigned g_sync[8192];   // 256 flags (8 sub-bg x 32 strips), 128B apart

__device__ __forceinline__ unsigned pk2(float x, float y){
    __nv_bfloat162 t=__floats2bfloat162_rn(x,y);
    return *(unsigned*)&t;
}
__device__ __forceinline__ void mma16(float* d, unsigned a0,unsigned a1,unsigned a2,
                                      unsigned a3, unsigned b0,unsigned b1){
    asm volatile("mma.sync.aligned.m16n8k16.row.col.f32.bf16.bf16.f32 "
        "{%0,%1,%2,%3}, {%4,%5,%6,%7}, {%8,%9}, {%0,%1,%2,%3};\n"
        : "+f"(d[0]),"+f"(d[1]),"+f"(d[2]),"+f"(d[3])
        : "r"(a0),"r"(a1),"r"(a2),"r"(a3),"r"(b0),"r"(b1));
}
__device__ __forceinline__ unsigned su32(const void* p){
    return (unsigned)__cvta_generic_to_shared(p);
}
__device__ __forceinline__ void cp16(unsigned dst, const void* src){
    asm volatile("cp.async.cg.shared.global [%0], [%1], 16;" :: "r"(dst), "l"(src));
}
__device__ __forceinline__ void cpc(){ asm volatile("cp.async.commit_group;"); }
template<int N> __device__ __forceinline__ void cpw(){
    asm volatile("cp.async.wait_group %0;" :: "n"(N));
}
__device__ __forceinline__ void barwg(int id){
    asm volatile("bar.sync %0, 128;" :: "r"(id) : "memory");
}
__device__ __forceinline__ float sigf(float x){ return 1.f/(1.f+__expf(-x)); }
__device__ __forceinline__ float tanhf_(float x){
    float e=__expf(-2.f*fabsf(x)); return copysignf((1.f-e)/(1.f+e), x);
}

// ---------------- prep ----------------
__global__ void prep_k(const float* __restrict__ xc, const int* __restrict__ c0,
                       const int* __restrict__ c1, const float* __restrict__ e0,
                       const float* __restrict__ e1, const float* __restrict__ Wk1,
                       const float* __restrict__ Wk2){
    const size_t N1=(size_t)RWS*64, N2=N1+32*G4, NT=N2+(size_t)256*G4;
    for(size_t i=(size_t)blockIdx.x*blockDim.x+threadIdx.x; i<NT;
        i+=(size_t)gridDim.x*blockDim.x){
        if(i<N1){
            int r=(int)(i>>6), cc=(int)(i&63), t=r>>8, b=r&255;
            float v=0.f;
            if(cc<8)       v=xc[(b*TST+t)*8+cc];
            else if(cc<40) v=e0[(size_t)c0[b*TST+t]*32+(cc-8)];
            else if(cc<56) v=e1[(size_t)c1[b*TST+t]*16+(cc-40)];
            g_X[i]=__float2bfloat16_rn(v);
        } else if(i<N2){
            size_t j=i-N1; int jr=(int)(j>>11), n=(int)(j&2047);
            float v0=(2*jr<56)?   Wk1[(size_t)(2*jr)*G4+n]   : 0.f;
            float v1=(2*jr+1<56)? Wk1[(size_t)(2*jr+1)*G4+n] : 0.f;
            g_Wk1p[j]=pk2(v0,v1);
        } else {
            size_t j=i-N2; int jr=(int)(j>>11), n=(int)(j&2047);
            g_Wk2r[j]=pk2(Wk2[(size_t)(2*jr)*G4+n], Wk2[(size_t)(2*jr+1)*G4+n]);
        }
    }
}

__global__ void zero_k(){
    int i=blockIdx.x*blockDim.x+threadIdx.x;
    if(i<2*32*BAT*8) ((unsigned*)g_Hb)[i]=0u;
}

__global__ void rst_k(){
    int i=blockIdx.x*blockDim.x+threadIdx.x;
    if(i<256) g_sync[i*32]=0u;
}

// ---------------- GEMM: C[M,2048] = A[M,K]@W[K,2048] + bias (bf16 in, f32 out)
__global__ __launch_bounds__(128) void gemm64(const __nv_bfloat16* __restrict__ A,
        const unsigned* __restrict__ Wp, const float* __restrict__ bias,
        float* __restrict__ C, int K){
    extern __shared__ float sm[];
    const int tid=threadIdx.x, l=tid&31, w=tid>>5, wm=w>>1, wn=w&1;
    const int g=l>>2, tg=l&3;
    const int row0=blockIdx.y*64, col0=blockIdx.x*64;
    float acc[2][4][4];
#pragma unroll
    for(int m=0;m<2;m++) for(int n=0;n<4;n++) for(int q=0;q<4;q++) acc[m][n][q]=0.f;
    const int NC=K>>6;

    auto issue=[&](int c){
        unsigned* Au=(unsigned*)(sm+(c&1)*4608);
        unsigned* Bu=Au+2304;
#pragma unroll
        for(int q=0;q<4;q++){ int e=tid+128*q, r=e>>3, s=e&7;
            cp16(su32(Au+r*36+s*4), A+(size_t)(row0+r)*K + c*64 + s*8); }
#pragma unroll
        for(int q=0;q<4;q++){ int e=tid+128*q, j=e>>4, s=e&15;
            cp16(su32(Bu+j*72+s*4), Wp+(size_t)(c*32+j)*G4 + col0 + s*4); }
    };
    issue(0); cpc();
    for(int c=0;c<NC;c++){
        if(c+1<NC){ issue(c+1); cpc(); cpw<1>(); } else cpw<0>();
        __syncthreads();
        const unsigned* Au=(const unsigned*)(sm+(c&1)*4608);
        const unsigned* Bu=Au+2304;
#pragma unroll
        for(int kb=0;kb<4;kb++){
            unsigned a[2][4];
#pragma unroll
            for(int mt=0;mt<2;mt++){
                int r=wm*32+mt*16+g;
                a[mt][0]=Au[r*36+kb*8+tg];       a[mt][1]=Au[(r+8)*36+kb*8+tg];
                a[mt][2]=Au[r*36+kb*8+tg+4];     a[mt][3]=Au[(r+8)*36+kb*8+tg+4];
            }
#pragma unroll
            for(int nt=0;nt<4;nt++){
                int cc=wn*32+nt*8+g;
                unsigned b0=Bu[(kb*8+tg)*72+cc], b1=Bu[(kb*8+tg+4)*72+cc];
                mma16(acc[0][nt],a[0][0],a[0][1],a[0][2],a[0][3],b0,b1);
                mma16(acc[1][nt],a[1][0],a[1][1],a[1][2],a[1][3],b0,b1);
            }
        }
        __syncthreads();
    }
#pragma unroll
    for(int nt=0;nt<4;nt++){
        int cc=col0+wn*32+nt*8+tg*2;
        float bx=bias[cc], by=bias[cc+1];
#pragma unroll
        for(int mt=0;mt<2;mt++){
            int r=row0+wm*32+mt*16+g;
            float2 v0={acc[mt][nt][0]+bx, acc[mt][nt][1]+by};
            float2 v1={acc[mt][nt][2]+bx, acc[mt][nt][3]+by};
            *(float2*)&C[(size_t)r*G4+cc]=v0;
            *(float2*)&C[(size_t)(r+8)*G4+cc]=v1;
        }
    }
}

// ---------------- persistent LSTM layer (bf16 mma, two-half pipeline) ----------------
// 128 CTAs = 4 bg x 32 strips; 8 sub-bgs of 32 rows; 512 thr = 4 wg (4-way K-split).
// SMEM: Wr 64KB | stages 64KB (wg x half x 2 chunks x 4KB) | red 32KB.
__global__ __launch_bounds__(512) void lstm_k(const float* __restrict__ xz,
        __nv_bfloat16* __restrict__ hout, const float* __restrict__ Wr,
        unsigned base){
    extern __shared__ float sm[];
    uint2* Wpk=(uint2*)sm;              // 8192 uint2 = 64 KB
    const int tid=threadIdx.x, l=tid&31, w=tid>>5;
    const int wg=w>>2, wl=w&3;
    const int wm=wl>>1, wn=wl&1;
    const int g=l>>2, tg=l&3;
    const int wtid=tid&127;
    const int strip=blockIdx.x&31, bg=blockIdx.x>>5;
    const int barid=wg+1;

    // prepack Wr slice (B-fragment lane order, same as R7)
    for(int e=tid;e<8192;e+=512){
        int tg_=e&3, ci=(e>>2)&63, kb=e>>8;
        int nt=ci>>4, wn_=(ci>>3)&1, gg=ci&7;
        int gcol=nt*HID + strip*16 + wn_*8 + gg;
        int k0=kb*16+tg_*2;
        uint2 v;
        v.x=pk2(Wr[(size_t)k0*G4+gcol],     Wr[(size_t)(k0+1)*G4+gcol]);
        v.y=pk2(Wr[(size_t)(k0+8)*G4+gcol], Wr[(size_t)(k0+9)*G4+gcol]);
        Wpk[e]=v;
    }
    __syncthreads();

    float cst[2][4];
#pragma unroll
    for(int h=0;h<2;h++) for(int q=0;q<4;q++) cst[h][q]=0.f;
    float xzp[2][4][4];

    auto pfxz=[&](int tt,int half){
        const float* xr=xz+(size_t)tt*BAT*G4;
        int b=(bg*2+half)*32 + wm*16 + g;
#pragma unroll
        for(int nt=0;nt<4;nt++){
            int cc=nt*HID+strip*16+wn*8+tg*2;
            float2 v0=*(const float2*)&xr[(size_t)b*G4+cc];
            float2 v1=*(const float2*)&xr[(size_t)(b+8)*G4+cc];
            xzp[half][nt][0]=v0.x; xzp[half][nt][1]=v0.y;
            xzp[half][nt][2]=v1.x; xzp[half][nt][3]=v1.y;
        }
    };
    if(wg==1){ pfxz(0,0); pfxz(0,1); }

    auto issueA=[&](const unsigned* hsrc,int half,int c){
        float* dst=sm+16384+wg*4096+half*2048+c*1024;
        const int sb=bg*2+half;
#pragma unroll
        for(int q=0;q<2;q++){
            int e=wtid+128*q;
            int kbl=e>>6, rem=e&63, r=rem>>1, hf=rem&1;
            int kb=wg*8+c*4+kbl;
            cp16(su32(dst+(kbl*32+r)*8+hf*4),
                 hsrc + ((size_t)(kb*BAT) + sb*32 + r)*8 + hf*4);
        }
    };

    // mma over one chunk of one half
    auto chunk=[&](float acc[4][4],int half,int c){
        const unsigned* Au=(const unsigned*)(sm+16384+wg*4096+half*2048+c*1024);
#pragma unroll
        for(int kbl=0;kbl<4;kbl++){
            const int kbg=wg*8+c*4+kbl;
            int r=wm*16+g;
            uint2 x0=*(const uint2*)&Au[(kbl*32+r)*8+tg*2];
            uint2 x1=*(const uint2*)&Au[(kbl*32+r+8)*8+tg*2];
#pragma unroll
            for(int nt=0;nt<4;nt++){
                uint2 bv=Wpk[(kbg*64 + nt*16+wn*8+g)*4 + tg];
                mma16(acc[nt], x0.x,x1.x,x0.y,x1.y, bv.x,bv.y);
            }
        }
    };

    auto reduce_epi=[&](float acc[4][4],int half,int t,unsigned* hn){
        if(wg!=0){
            float4* redw=(float4*)(sm+32768+wg*2048);
#pragma unroll
            for(int nt=0;nt<4;nt++){
                float4 v={acc[nt][0],acc[nt][1],acc[nt][2],acc[nt][3]};
                redw[wtid*4 + ((nt+wtid)&3)]=v;
            }
        }
        __syncthreads();
        if(wg==0){
            const int sb=bg*2+half;
#pragma unroll
            for(int nt=0;nt<4;nt++){
#pragma unroll
                for(int ww=1;ww<4;ww++){
                    const float4* redw=(const float4*)(sm+32768+ww*2048);
                    float4 v=redw[wtid*4 + ((nt+wtid)&3)];
                    acc[nt][0]+=v.x; acc[nt][1]+=v.y;
                    acc[nt][2]+=v.z; acc[nt][3]+=v.w;
                }
            }
            float hq[2][2];
#pragma unroll
            for(int q=0;q<4;q++){
                float ig=sigf(acc[0][q]);
                float fg=sigf(acc[1][q]);
                float gv=tanhf_(acc[2][q]);
                float og=sigf(acc[3][q]);
                float cc_=fg*cst[half][q]+ig*gv;
                cst[half][q]=cc_;
                hq[q>>1][q&1]=og*tanhf_(cc_);
            }
#pragma unroll
            for(int p=0;p<2;p++){
                int b=sb*32+wm*16+p*8+g;
                int U0=strip*16+wn*8+tg*2;
                unsigned pv=pk2(hq[p][0],hq[p][1]);
                *(unsigned*)&hout[(size_t)(t*BAT+b)*HID+U0]=pv;
                hn[((size_t)(strip*BAT)+b)*8 + tg*2 + wn]=pv;
            }
            barwg(1);
            if(tid==0){
                __threadfence();
                g_sync[(sb*32+strip)*32]=base+(unsigned)(t+1);
            }
        }
    };

    // pre-loop: issue half0 stages for t=0 (g_Hb[0] pre-zeroed)
    { const unsigned* hb0=g_Hb[0];
      issueA(hb0,0,0); cpc(); issueA(hb0,0,1); cpc(); }

    for(int t=0;t<TST;t++){
        const unsigned* hb=g_Hb[t&1];
        unsigned* hn=g_Hb[(t&1)^1];

        // wait peers half1(t-1); issue half1 h loads (hidden behind half0 compute)
        if(tid<32){
            const volatile unsigned* f=&g_sync[((bg*2+1)*32+tid)*32];
            unsigned tgt=base+(unsigned)t;
            while(*f<tgt){}
        }
        __threadfence(); __syncthreads();
        issueA(hb,1,0); cpc(); issueA(hb,1,1); cpc();

        // ---- half0 ----
        float acc[4][4];
        if(wg==1){
#pragma unroll
            for(int nt=0;nt<4;nt++) for(int q=0;q<4;q++) acc[nt][q]=xzp[0][nt][q];
        } else {
#pragma unroll
            for(int nt=0;nt<4;nt++) for(int q=0;q<4;q++) acc[nt][q]=0.f;
        }
        cpw<3>(); barwg(barid); chunk(acc,0,0);
        cpw<2>(); barwg(barid); chunk(acc,0,1);
        barwg(barid);                       // wg done reading half0 stages
        reduce_epi(acc,0,t,hn);
        if(wg==1 && t+1<TST) pfxz(t+1,0);

        // wait peers half0(t); issue half0 h loads for t+1 (hidden behind half1)
        if(t+1<TST){
            if(tid<32){
                const volatile unsigned* f=&g_sync[((bg*2+0)*32+tid)*32];
                unsigned tgt=base+(unsigned)(t+1);
                while(*f<tgt){}
            }
            __threadfence(); __syncthreads();
            issueA(hn,0,0); cpc(); issueA(hn,0,1); cpc();
        }

        // ---- half1 ----
        if(wg==1){
#pragma unroll
            for(int nt=0;nt<4;nt++) for(int q=0;q<4;q++) acc[nt][q]=xzp[1][nt][q];
        } else {
#pragma unroll
            for(int nt=0;nt<4;nt++) for(int q=0;q<4;q++) acc[nt][q]=0.f;
        }
        if(t+1<TST){ cpw<3>(); } else { cpw<1>(); }
        barwg(barid); chunk(acc,1,0);
        if(t+1<TST){ cpw<2>(); } else { cpw<0>(); }
        barwg(barid); chunk(acc,1,1);
        barwg(barid);
        reduce_epi(acc,1,t,hn);
        if(wg==1 && t+1<TST) pfxz(t+1,1);
    }
}

// ---------------- heads ----------------
__global__ __launch_bounds__(256) void head_k(const __nv_bfloat16* __restrict__ h,
        const float* __restrict__ Wmu, const float* __restrict__ bmu,
        const float* __restrict__ Wsig, const float* __restrict__ bsig,
        float* __restrict__ out){
    int w=threadIdx.x>>5, l=threadIdx.x&31;
    int r=blockIdx.x*8+w;
    const __nv_bfloat16* hr=h+(size_t)r*HID;
    float smu=0.f, ssg=0.f;
    for(int k=l;k<HID;k+=32){
        float hv=__bfloat162float(hr[k]);
        smu+=hv*Wmu[k]; ssg+=hv*Wsig[k];
    }
#pragma unroll
    for(int o=16;o;o>>=1){
        smu+=__shfl_xor_sync(0xFFFFFFFFu,smu,o);
        ssg+=__shfl_xor_sync(0xFFFFFFFFu,ssg,o);
    }
    if(l==0){
        int t=r>>8, b=r&255;
        out[b*TST+t]=smu+bmu[0];
        float x=ssg+bsig[0];
        out[RWS + b*TST+t]=(x>20.f)? x : log1pf(__expf(x));
    }
}

extern "C" void kernel_launch(void* const* d_in, const int* in_sizes, int n_in,
                              void* d_out, int out_size){
    const float* xc  =(const float*)d_in[0];
    const int*   c0  =(const int*  )d_in[1];
    const int*   c1  =(const int*  )d_in[2];
    const float* e0  =(const float*)d_in[3];
    const float* e1  =(const float*)d_in[4];
    const float* Wk1 =(const float*)d_in[5];
    const float* Wr1 =(const float*)d_in[6];
    const float* b1  =(const float*)d_in[7];
    const float* Wk2 =(const float*)d_in[8];
    const float* Wr2 =(const float*)d_in[9];
    const float* b2  =(const float*)d_in[10];
    const float* Wmu =(const float*)d_in[11];
    const float* bmu =(const float*)d_in[12];
    const float* Wsig=(const float*)d_in[13];
    const float* bsig=(const float*)d_in[14];
    float* out=(float*)d_out;

    cudaFuncSetAttribute(lstm_k, cudaFuncAttributeMaxDynamicSharedMemorySize, 163840);
    cudaFuncSetAttribute(gemm64, cudaFuncAttributeMaxDynamicSharedMemorySize, 36864);

    void *pX,*pXZ,*pH1,*pH2,*pW1,*pW2;
    cudaGetSymbolAddress(&pX,  g_X);
    cudaGetSymbolAddress(&pXZ, g_XZ);
    cudaGetSymbolAddress(&pH1, g_H1);
    cudaGetSymbolAddress(&pH2, g_H2);
    cudaGetSymbolAddress(&pW1, g_Wk1p);
    cudaGetSymbolAddress(&pW2, g_Wk2r);

    prep_k<<<4096,256>>>(xc,c0,c1,e0,e1,Wk1,Wk2);
    zero_k<<<512,256>>>();
    gemm64<<<dim3(32,RWS/64),128,36864>>>((const __nv_bfloat16*)pX,
        (const unsigned*)pW1,b1,(float*)pXZ,64);
    lstm_k<<<128,512,163840>>>((const float*)pXZ,(__nv_bfloat16*)pH1,Wr1,0u);
    zero_k<<<512,256>>>();
    gemm64<<<dim3(32,RWS/64),128,36864>>>((const __nv_bfloat16*)pH1,
        (const unsigned*)pW2,b2,(float*)pXZ,512);
    lstm_k<<<128,512,163840>>>((const float*)pXZ,(__nv_bfloat16*)pH2,Wr2,192u);
    head_k<<<RWS/8,256>>>((const __nv_bfloat16*)pH2,Wmu,bmu,Wsig,bsig,out);
    rst_k<<<1,256>>>();
}

// round 9
// speedup vs baseline: 1.0296x; 1.0296x over previous
#include <cuda_runtime.h>
#include <cuda_bf16.h>
#include <cstdint>
#include <cstddef>

#define TST 192
#define BAT 256
#define HID 512
#define G4  2048
#define RWS (TST*BAT)

__device__ __nv_bfloat16 g_X[(size_t)RWS*64];
__device__ float g_XZ[(size_t)RWS*G4];
__device__ __nv_bfloat16 g_H1[(size_t)RWS*HID];
__device__ __nv_bfloat16 g_H2[(size_t)RWS*HID];
__device__ unsigned g_Hb[2][32*BAT*8];   // packed bf16 h ping-pong [kb16][b][8 u32]
__device__ unsigned g_Wk1p[32*G4];
__device__ unsigned g_Wk2r[256*G4];
__device__ volatile unsigned g_sync[8192];   // 256 flags (8 sub-bg x 32 strips), 128B apart

__device__ __forceinline__ unsigned pk2(float x, float y){
    __nv_bfloat162 t=__floats2bfloat162_rn(x,y);
    return *(unsigned*)&t;
}
__device__ __forceinline__ void mma16(float* d, unsigned a0,unsigned a1,unsigned a2,
                                      unsigned a3, unsigned b0,unsigned b1){
    asm volatile("mma.sync.aligned.m16n8k16.row.col.f32.bf16.bf16.f32 "
        "{%0,%1,%2,%3}, {%4,%5,%6,%7}, {%8,%9}, {%0,%1,%2,%3};\n"
        : "+f"(d[0]),"+f"(d[1]),"+f"(d[2]),"+f"(d[3])
        : "r"(a0),"r"(a1),"r"(a2),"r"(a3),"r"(b0),"r"(b1));
}
__device__ __forceinline__ unsigned su32(const void* p){
    return (unsigned)__cvta_generic_to_shared(p);
}
__device__ __forceinline__ void cp16(unsigned dst, const void* src){
    asm volatile("cp.async.cg.shared.global [%0], [%1], 16;" :: "r"(dst), "l"(src));
}
__device__ __forceinline__ void cpc(){ asm volatile("cp.async.commit_group;"); }
template<int N> __device__ __forceinline__ void cpw(){
    asm volatile("cp.async.wait_group %0;" :: "n"(N));
}
__device__ __forceinline__ void barwg(int id){
    asm volatile("bar.sync %0, 128;" :: "r"(id) : "memory");
}
__device__ __forceinline__ float sigf(float x){ return 1.f/(1.f+__expf(-x)); }
__device__ __forceinline__ float tanhf_(float x){
    float e=__expf(-2.f*fabsf(x)); return copysignf((1.f-e)/(1.f+e), x);
}

// ---------------- prep ----------------
__global__ void prep_k(const float* __restrict__ xc, const int* __restrict__ c0,
                       const int* __restrict__ c1, const float* __restrict__ e0,
                       const float* __restrict__ e1, const float* __restrict__ Wk1,
                       const float* __restrict__ Wk2){
    const size_t N1=(size_t)RWS*64, N2=N1+32*G4, NT=N2+(size_t)256*G4;
    for(size_t i=(size_t)blockIdx.x*blockDim.x+threadIdx.x; i<NT;
        i+=(size_t)gridDim.x*blockDim.x){
        if(i<N1){
            int r=(int)(i>>6), cc=(int)(i&63), t=r>>8, b=r&255;
            float v=0.f;
            if(cc<8)       v=xc[(b*TST+t)*8+cc];
            else if(cc<40) v=e0[(size_t)c0[b*TST+t]*32+(cc-8)];
            else if(cc<56) v=e1[(size_t)c1[b*TST+t]*16+(cc-40)];
            g_X[i]=__float2bfloat16_rn(v);
        } else if(i<N2){
            size_t j=i-N1; int jr=(int)(j>>11), n=(int)(j&2047);
            float v0=(2*jr<56)?   Wk1[(size_t)(2*jr)*G4+n]   : 0.f;
            float v1=(2*jr+1<56)? Wk1[(size_t)(2*jr+1)*G4+n] : 0.f;
            g_Wk1p[j]=pk2(v0,v1);
        } else {
            size_t j=i-N2; int jr=(int)(j>>11), n=(int)(j&2047);
            g_Wk2r[j]=pk2(Wk2[(size_t)(2*jr)*G4+n], Wk2[(size_t)(2*jr+1)*G4+n]);
        }
    }
}

__global__ void zero_k(){
    int i=blockIdx.x*blockDim.x+threadIdx.x;
    if(i<2*32*BAT*8) ((unsigned*)g_Hb)[i]=0u;
}

__global__ void rst_k(){
    int i=blockIdx.x*blockDim.x+threadIdx.x;
    if(i<256) g_sync[i*32]=0u;
}

// ---------------- GEMM: C[M,2048] = A[M,K]@W[K,2048] + bias (bf16 in, f32 out)
__global__ __launch_bounds__(128) void gemm64(const __nv_bfloat16* __restrict__ A,
        const unsigned* __restrict__ Wp, const float* __restrict__ bias,
        float* __restrict__ C, int K){
    extern __shared__ float sm[];
    const int tid=threadIdx.x, l=tid&31, w=tid>>5, wm=w>>1, wn=w&1;
    const int g=l>>2, tg=l&3;
    const int row0=blockIdx.y*64, col0=blockIdx.x*64;
    float acc[2][4][4];
#pragma unroll
    for(int m=0;m<2;m++) for(int n=0;n<4;n++) for(int q=0;q<4;q++) acc[m][n][q]=0.f;
    const int NC=K>>6;

    auto issue=[&](int c){
        unsigned* Au=(unsigned*)(sm+(c&1)*4608);
        unsigned* Bu=Au+2304;
#pragma unroll
        for(int q=0;q<4;q++){ int e=tid+128*q, r=e>>3, s=e&7;
            cp16(su32(Au+r*36+s*4), A+(size_t)(row0+r)*K + c*64 + s*8); }
#pragma unroll
        for(int q=0;q<4;q++){ int e=tid+128*q, j=e>>4, s=e&15;
            cp16(su32(Bu+j*72+s*4), Wp+(size_t)(c*32+j)*G4 + col0 + s*4); }
    };
    issue(0); cpc();
    for(int c=0;c<NC;c++){
        if(c+1<NC){ issue(c+1); cpc(); cpw<1>(); } else cpw<0>();
        __syncthreads();
        const unsigned* Au=(const unsigned*)(sm+(c&1)*4608);
        const unsigned* Bu=Au+2304;
#pragma unroll
        for(int kb=0;kb<4;kb++){
            unsigned a[2][4];
#pragma unroll
            for(int mt=0;mt<2;mt++){
                int r=wm*32+mt*16+g;
                a[mt][0]=Au[r*36+kb*8+tg];       a[mt][1]=Au[(r+8)*36+kb*8+tg];
                a[mt][2]=Au[r*36+kb*8+tg+4];     a[mt][3]=Au[(r+8)*36+kb*8+tg+4];
            }
#pragma unroll
            for(int nt=0;nt<4;nt++){
                int cc=wn*32+nt*8+g;
                unsigned b0=Bu[(kb*8+tg)*72+cc], b1=Bu[(kb*8+tg+4)*72+cc];
                mma16(acc[0][nt],a[0][0],a[0][1],a[0][2],a[0][3],b0,b1);
                mma16(acc[1][nt],a[1][0],a[1][1],a[1][2],a[1][3],b0,b1);
            }
        }
        __syncthreads();
    }
#pragma unroll
    for(int nt=0;nt<4;nt++){
        int cc=col0+wn*32+nt*8+tg*2;
        float bx=bias[cc], by=bias[cc+1];
#pragma unroll
        for(int mt=0;mt<2;mt++){
            int r=row0+wm*32+mt*16+g;
            float2 v0={acc[mt][nt][0]+bx, acc[mt][nt][1]+by};
            float2 v1={acc[mt][nt][2]+bx, acc[mt][nt][3]+by};
            *(float2*)&C[(size_t)r*G4+cc]=v0;
            *(float2*)&C[(size_t)(r+8)*G4+cc]=v1;
        }
    }
}

// ---------------- persistent LSTM layer (bf16 mma, two-half pipeline) ----------------
// 128 CTAs = 4 bg x 32 strips; 8 sub-bgs of 32 rows; 512 thr = 4 wg (4-way K-split).
// SMEM: Wr 64KB | stages 64KB (wg x half x 2 chunks x 4KB) | red 32KB.
__global__ __launch_bounds__(512) void lstm_k(const float* __restrict__ xz,
        __nv_bfloat16* __restrict__ hout, const float* __restrict__ Wr,
        unsigned base){
    extern __shared__ float sm[];
    uint2* Wpk=(uint2*)sm;              // 8192 uint2 = 64 KB
    const int tid=threadIdx.x, l=tid&31, w=tid>>5;
    const int wg=w>>2, wl=w&3;
    const int wm=wl>>1, wn=wl&1;
    const int g=l>>2, tg=l&3;
    const int wtid=tid&127;
    const int strip=blockIdx.x&31, bg=blockIdx.x>>5;
    const int barid=wg+1;

    // prepack Wr slice (B-fragment lane order, same as R7)
    for(int e=tid;e<8192;e+=512){
        int tg_=e&3, ci=(e>>2)&63, kb=e>>8;
        int nt=ci>>4, wn_=(ci>>3)&1, gg=ci&7;
        int gcol=nt*HID + strip*16 + wn_*8 + gg;
        int k0=kb*16+tg_*2;
        uint2 v;
        v.x=pk2(Wr[(size_t)k0*G4+gcol],     Wr[(size_t)(k0+1)*G4+gcol]);
        v.y=pk2(Wr[(size_t)(k0+8)*G4+gcol], Wr[(size_t)(k0+9)*G4+gcol]);
        Wpk[e]=v;
    }
    __syncthreads();

    float cst[2][4];
#pragma unroll
    for(int h=0;h<2;h++) for(int q=0;q<4;q++) cst[h][q]=0.f;
    float xzp[2][4][4];

    auto pfxz=[&](int tt,int half){
        const float* xr=xz+(size_t)tt*BAT*G4;
        int b=(bg*2+half)*32 + wm*16 + g;
#pragma unroll
        for(int nt=0;nt<4;nt++){
            int cc=nt*HID+strip*16+wn*8+tg*2;
            float2 v0=*(const float2*)&xr[(size_t)b*G4+cc];
            float2 v1=*(const float2*)&xr[(size_t)(b+8)*G4+cc];
            xzp[half][nt][0]=v0.x; xzp[half][nt][1]=v0.y;
            xzp[half][nt][2]=v1.x; xzp[half][nt][3]=v1.y;
        }
    };
    if(wg==1){ pfxz(0,0); pfxz(0,1); }

    auto issueA=[&](const unsigned* hsrc,int half,int c){
        float* dst=sm+16384+wg*4096+half*2048+c*1024;
        const int sb=bg*2+half;
#pragma unroll
        for(int q=0;q<2;q++){
            int e=wtid+128*q;
            int kbl=e>>6, rem=e&63, r=rem>>1, hf=rem&1;
            int kb=wg*8+c*4+kbl;
            cp16(su32(dst+(kbl*32+r)*8+hf*4),
                 hsrc + ((size_t)(kb*BAT) + sb*32 + r)*8 + hf*4);
        }
    };

    // mma over one chunk of one half
    auto chunk=[&](float acc[4][4],int half,int c){
        const unsigned* Au=(const unsigned*)(sm+16384+wg*4096+half*2048+c*1024);
#pragma unroll
        for(int kbl=0;kbl<4;kbl++){
            const int kbg=wg*8+c*4+kbl;
            int r=wm*16+g;
            uint2 x0=*(const uint2*)&Au[(kbl*32+r)*8+tg*2];
            uint2 x1=*(const uint2*)&Au[(kbl*32+r+8)*8+tg*2];
#pragma unroll
            for(int nt=0;nt<4;nt++){
                uint2 bv=Wpk[(kbg*64 + nt*16+wn*8+g)*4 + tg];
                mma16(acc[nt], x0.x,x1.x,x0.y,x1.y, bv.x,bv.y);
            }
        }
    };

    auto reduce_epi=[&](float acc[4][4],int half,int t,unsigned* hn){
        if(wg!=0){
            float4* redw=(float4*)(sm+32768+wg*2048);
#pragma unroll
            for(int nt=0;nt<4;nt++){
                float4 v={acc[nt][0],acc[nt][1],acc[nt][2],acc[nt][3]};
                redw[wtid*4 + ((nt+wtid)&3)]=v;
            }
        }
        __syncthreads();
        if(wg==0){
            const int sb=bg*2+half;
#pragma unroll
            for(int nt=0;nt<4;nt++){
#pragma unroll
                for(int ww=1;ww<4;ww++){
                    const float4* redw=(const float4*)(sm+32768+ww*2048);
                    float4 v=redw[wtid*4 + ((nt+wtid)&3)];
                    acc[nt][0]+=v.x; acc[nt][1]+=v.y;
                    acc[nt][2]+=v.z; acc[nt][3]+=v.w;
                }
            }
            float hq[2][2];
#pragma unroll
            for(int q=0;q<4;q++){
                float ig=sigf(acc[0][q]);
                float fg=sigf(acc[1][q]);
                float gv=tanhf_(acc[2][q]);
                float og=sigf(acc[3][q]);
                float cc_=fg*cst[half][q]+ig*gv;
                cst[half][q]=cc_;
                hq[q>>1][q&1]=og*tanhf_(cc_);
            }
#pragma unroll
            for(int p=0;p<2;p++){
                int b=sb*32+wm*16+p*8+g;
                int U0=strip*16+wn*8+tg*2;
                unsigned pv=pk2(hq[p][0],hq[p][1]);
                *(unsigned*)&hout[(size_t)(t*BAT+b)*HID+U0]=pv;
                hn[((size_t)(strip*BAT)+b)*8 + tg*2 + wn]=pv;
            }
            barwg(1);
            if(tid==0){
                __threadfence();
                g_sync[(sb*32+strip)*32]=base+(unsigned)(t+1);
            }
        }
    };

    // pre-loop: issue half0 stages for t=0 (g_Hb[0] pre-zeroed)
    { const unsigned* hb0=g_Hb[0];
      issueA(hb0,0,0); cpc(); issueA(hb0,0,1); cpc(); }

    for(int t=0;t<TST;t++){
        const unsigned* hb=g_Hb[t&1];
        unsigned* hn=g_Hb[(t&1)^1];

        // wait peers half1(t-1); issue half1 h loads (hidden behind half0 compute)
        if(tid<32){
            const volatile unsigned* f=&g_sync[((bg*2+1)*32+tid)*32];
            unsigned tgt=base+(unsigned)t;
            while(*f<tgt){}
        }
        __threadfence(); __syncthreads();
        issueA(hb,1,0); cpc(); issueA(hb,1,1); cpc();

        // ---- half0 ----
        float acc[4][4];
        if(wg==1){
#pragma unroll
            for(int nt=0;nt<4;nt++) for(int q=0;q<4;q++) acc[nt][q]=xzp[0][nt][q];
        } else {
#pragma unroll
            for(int nt=0;nt<4;nt++) for(int q=0;q<4;q++) acc[nt][q]=0.f;
        }
        cpw<3>(); barwg(barid); chunk(acc,0,0);
        cpw<2>(); barwg(barid); chunk(acc,0,1);
        barwg(barid);                       // wg done reading half0 stages
        reduce_epi(acc,0,t,hn);
        if(wg==1 && t+1<TST) pfxz(t+1,0);

        // wait peers half0(t); issue half0 h loads for t+1 (hidden behind half1)
        if(t+1<TST){
            if(tid<32){
                const volatile unsigned* f=&g_sync[((bg*2+0)*32+tid)*32];
                unsigned tgt=base+(unsigned)(t+1);
                while(*f<tgt){}
            }
            __threadfence(); __syncthreads();
            issueA(hn,0,0); cpc(); issueA(hn,0,1); cpc();
        }

        // ---- half1 ----
        if(wg==1){
#pragma unroll
            for(int nt=0;nt<4;nt++) for(int q=0;q<4;q++) acc[nt][q]=xzp[1][nt][q];
        } else {
#pragma unroll
            for(int nt=0;nt<4;nt++) for(int q=0;q<4;q++) acc[nt][q]=0.f;
        }
        if(t+1<TST){ cpw<3>(); } else { cpw<1>(); }
        barwg(barid); chunk(acc,1,0);
        if(t+1<TST){ cpw<2>(); } else { cpw<0>(); }
        barwg(barid); chunk(acc,1,1);
        barwg(barid);
        reduce_epi(acc,1,t,hn);
        if(wg==1 && t+1<TST) pfxz(t+1,1);
    }
}

// ---------------- heads ----------------
__global__ __launch_bounds__(256) void head_k(const __nv_bfloat16* __restrict__ h,
        const float* __restrict__ Wmu, const float* __restrict__ bmu,
        const float* __restrict__ Wsig, const float* __restrict__ bsig,
        float* __restrict__ out){
    int w=threadIdx.x>>5, l=threadIdx.x&31;
    int r=blockIdx.x*8+w;
    const __nv_bfloat16* hr=h+(size_t)r*HID;
    float smu=0.f, ssg=0.f;
    for(int k=l;k<HID;k+=32){
        float hv=__bfloat162float(hr[k]);
        smu+=hv*Wmu[k]; ssg+=hv*Wsig[k];
    }
#pragma unroll
    for(int o=16;o;o>>=1){
        smu+=__shfl_xor_sync(0xFFFFFFFFu,smu,o);
        ssg+=__shfl_xor_sync(0xFFFFFFFFu,ssg,o);
    }
    if(l==0){
        int t=r>>8, b=r&255;
        out[b*TST+t]=smu+bmu[0];
        float x=ssg+bsig[0];
        out[RWS + b*TST+t]=(x>20.f)? x : log1pf(__expf(x));
    }
}

extern "C" void kernel_launch(void* const* d_in, const int* in_sizes, int n_in,
                              void* d_out, int out_size){
    const float* xc  =(const float*)d_in[0];
    const int*   c0  =(const int*  )d_in[1];
    const int*   c1  =(const int*  )d_in[2];
    const float* e0  =(const float*)d_in[3];
    const float* e1  =(const float*)d_in[4];
    const float* Wk1 =(const float*)d_in[5];
    const float* Wr1 =(const float*)d_in[6];
    const float* b1  =(const float*)d_in[7];
    const float* Wk2 =(const float*)d_in[8];
    const float* Wr2 =(const float*)d_in[9];
    const float* b2  =(const float*)d_in[10];
    const float* Wmu =(const float*)d_in[11];
    const float* bmu =(const float*)d_in[12];
    const float* Wsig=(const float*)d_in[13];
    const float* bsig=(const float*)d_in[14];
    float* out=(float*)d_out;

    cudaFuncSetAttribute(lstm_k, cudaFuncAttributeMaxDynamicSharedMemorySize, 163840);
    cudaFuncSetAttribute(gemm64, cudaFuncAttributeMaxDynamicSharedMemorySize, 36864);

    void *pX,*pXZ,*pH1,*pH2,*pW1,*pW2;
    cudaGetSymbolAddress(&pX,  g_X);
    cudaGetSymbolAddress(&pXZ, g_XZ);
    cudaGetSymbolAddress(&pH1, g_H1);
    cudaGetSymbolAddress(&pH2, g_H2);
    cudaGetSymbolAddress(&pW1, g_Wk1p);
    cudaGetSymbolAddress(&pW2, g_Wk2r);

    prep_k<<<4096,256>>>(xc,c0,c1,e0,e1,Wk1,Wk2);
    zero_k<<<512,256>>>();
    gemm64<<<dim3(32,RWS/64),128,36864>>>((const __nv_bfloat16*)pX,
        (const unsigned*)pW1,b1,(float*)pXZ,64);
    lstm_k<<<128,512,163840>>>((const float*)pXZ,(__nv_bfloat16*)pH1,Wr1,0u);
    zero_k<<<512,256>>>();
    gemm64<<<dim3(32,RWS/64),128,36864>>>((const __nv_bfloat16*)pH1,
        (const unsigned*)pW2,b2,(float*)pXZ,512);
    lstm_k<<<128,512,163840>>>((const float*)pXZ,(__nv_bfloat16*)pH2,Wr2,192u);
    head_k<<<RWS/8,256>>>((const __nv_bfloat16*)pH2,Wmu,bmu,Wsig,bsig,out);
    rst_k<<<1,256>>>();
}

// round 11
// speedup vs baseline: 1.6550x; 1.6074x over previous
#include <cuda_runtime.h>
#include <cuda_bf16.h>
#include <cstdint>
#include <cstddef>

#define TST 192
#define BAT 256
#define HID 512
#define G4  2048
#define RWS (TST*BAT)

__device__ __nv_bfloat16 g_X[(size_t)RWS*64];
__device__ float g_XZ[(size_t)RWS*G4];
__device__ unsigned g_H1p[(size_t)TST*32*BAT*8]; // packed h1 per step [t][kb][b][8]
__device__ __nv_bfloat16 g_H2[(size_t)RWS*HID];
__device__ unsigned g_Hb1[2][32*BAT*8];
__device__ unsigned g_Hb2[2][32*BAT*8];
__device__ unsigned g_Wk1p[32*G4];
__device__ volatile unsigned g_sync[4096];

__device__ __forceinline__ unsigned pk2(float x, float y){
    __nv_bfloat162 t=__floats2bfloat162_rn(x,y);
    return *(unsigned*)&t;
}
__device__ __forceinline__ void mma16(float* d, unsigned a0,unsigned a1,unsigned a2,
                                      unsigned a3, unsigned b0,unsigned b1){
    asm volatile("mma.sync.aligned.m16n8k16.row.col.f32.bf16.bf16.f32 "
        "{%0,%1,%2,%3}, {%4,%5,%6,%7}, {%8,%9}, {%0,%1,%2,%3};\n"
        : "+f"(d[0]),"+f"(d[1]),"+f"(d[2]),"+f"(d[3])
        : "r"(a0),"r"(a1),"r"(a2),"r"(a3),"r"(b0),"r"(b1));
}
__device__ __forceinline__ unsigned su32(const void* p){
    return (unsigned)__cvta_generic_to_shared(p);
}
__device__ __forceinline__ void cp16(unsigned dst, const void* src){
    asm volatile("cp.async.cg.shared.global [%0], [%1], 16;" :: "r"(dst), "l"(src));
}
__device__ __forceinline__ void cpc(){ asm volatile("cp.async.commit_group;"); }
template<int N> __device__ __forceinline__ void cpw(){
    asm volatile("cp.async.wait_group %0;" :: "n"(N));
}
__device__ __forceinline__ void barwg(int id){
    asm volatile("bar.sync %0, 128;" :: "r"(id) : "memory");
}
__device__ __forceinline__ float tanha(float x){
    float r; asm("tanh.approx.f32 %0,%1;" : "=f"(r) : "f"(x)); return r;
}
__device__ __forceinline__ float siga(float x){ return fmaf(tanha(x*0.5f),0.5f,0.5f); }

// ---------------- prep ----------------
__global__ void prep_k(const float* __restrict__ xc, const int* __restrict__ c0,
                       const int* __restrict__ c1, const float* __restrict__ e0,
                       const float* __restrict__ e1, const float* __restrict__ Wk1){
    const size_t N1=(size_t)RWS*64, NT=N1+32*G4;
    for(size_t i=(size_t)blockIdx.x*blockDim.x+threadIdx.x; i<NT;
        i+=(size_t)gridDim.x*blockDim.x){
        if(i<N1){
            int r=(int)(i>>6), cc=(int)(i&63), t=r>>8, b=r&255;
            float v=0.f;
            if(cc<8)       v=xc[(b*TST+t)*8+cc];
            else if(cc<40) v=e0[(size_t)c0[b*TST+t]*32+(cc-8)];
            else if(cc<56) v=e1[(size_t)c1[b*TST+t]*16+(cc-40)];
            g_X[i]=__float2bfloat16_rn(v);
        } else {
            size_t j=i-N1; int jr=(int)(j>>11), n=(int)(j&2047);
            float v0=(2*jr<56)?   Wk1[(size_t)(2*jr)*G4+n]   : 0.f;
            float v1=(2*jr+1<56)? Wk1[(size_t)(2*jr+1)*G4+n] : 0.f;
            g_Wk1p[j]=pk2(v0,v1);
        }
    }
}

__global__ void zero_k(){
    int i=blockIdx.x*blockDim.x+threadIdx.x;
    if(i<131072) ((unsigned*)g_Hb1)[i]=0u;
    else if(i<262144) ((unsigned*)g_Hb2)[i-131072]=0u;
}

__global__ void rst_k(){
    if(threadIdx.x<128) g_sync[threadIdx.x*32]=0u;
}

// ---------------- GEMM1: xz1 = X@Wk1 + b1 (K=64) ----------------
__global__ __launch_bounds__(128) void gemm64(const __nv_bfloat16* __restrict__ A,
        const unsigned* __restrict__ Wp, const float* __restrict__ bias,
        float* __restrict__ C, int K){
    extern __shared__ float sm[];
    const int tid=threadIdx.x, l=tid&31, w=tid>>5, wm=w>>1, wn=w&1;
    const int g=l>>2, tg=l&3;
    const int row0=blockIdx.y*64, col0=blockIdx.x*64;
    float acc[2][4][4];
#pragma unroll
    for(int m=0;m<2;m++) for(int n=0;n<4;n++) for(int q=0;q<4;q++) acc[m][n][q]=0.f;
    const int NC=K>>6;
    auto issue=[&](int c){
        unsigned* Au=(unsigned*)(sm+(c&1)*4608);
        unsigned* Bu=Au+2304;
#pragma unroll
        for(int q=0;q<4;q++){ int e=tid+128*q, r=e>>3, s=e&7;
            cp16(su32(Au+r*36+s*4), A+(size_t)(row0+r)*K + c*64 + s*8); }
#pragma unroll
        for(int q=0;q<4;q++){ int e=tid+128*q, j=e>>4, s=e&15;
            cp16(su32(Bu+j*72+s*4), Wp+(size_t)(c*32+j)*G4 + col0 + s*4); }
    };
    issue(0); cpc();
    for(int c=0;c<NC;c++){
        if(c+1<NC){ issue(c+1); cpc(); cpw<1>(); } else cpw<0>();
        __syncthreads();
        const unsigned* Au=(const unsigned*)(sm+(c&1)*4608);
        const unsigned* Bu=Au+2304;
#pragma unroll
        for(int kb=0;kb<4;kb++){
            unsigned a[2][4];
#pragma unroll
            for(int mt=0;mt<2;mt++){
                int r=wm*32+mt*16+g;
                a[mt][0]=Au[r*36+kb*8+tg];   a[mt][1]=Au[(r+8)*36+kb*8+tg];
                a[mt][2]=Au[r*36+kb*8+tg+4]; a[mt][3]=Au[(r+8)*36+kb*8+tg+4];
            }
#pragma unroll
            for(int nt=0;nt<4;nt++){
                int cc=wn*32+nt*8+g;
                unsigned b0=Bu[(kb*8+tg)*72+cc], b1=Bu[(kb*8+tg+4)*72+cc];
                mma16(acc[0][nt],a[0][0],a[0][1],a[0][2],a[0][3],b0,b1);
                mma16(acc[1][nt],a[1][0],a[1][1],a[1][2],a[1][3],b0,b1);
            }
        }
        __syncthreads();
    }
#pragma unroll
    for(int nt=0;nt<4;nt++){
        int cc=col0+wn*32+nt*8+tg*2;
        float bx=bias[cc], by=bias[cc+1];
#pragma unroll
        for(int mt=0;mt<2;mt++){
            int r=row0+wm*32+mt*16+g;
            float2 v0={acc[mt][nt][0]+bx, acc[mt][nt][1]+by};
            float2 v1={acc[mt][nt][2]+bx, acc[mt][nt][3]+by};
            *(float2*)&C[(size_t)r*G4+cc]=v0;
            *(float2*)&C[(size_t)(r+8)*G4+cc]=v1;
        }
    }
}

// ---------------- unified persistent LSTM ----------------
// KBW = kb16 blocks per wg. SEC: K=1024=[h1(t);h2(t-1)] (gemm2 folded in).
// SMEM: Wpk (NKB*2KB) | per-wg 3x2KB stage bufs. Red reuses stages:
//   SEC red = buf1+buf2 (stg+2048), L1 red = buf0+buf1 (stg).
template<int KBW, bool SEC>
__global__ __launch_bounds__(512) void lstm_t(const float* __restrict__ xz,
        const float* __restrict__ W0, const float* __restrict__ W1,
        const float* __restrict__ bias, unsigned base){
    extern __shared__ float sm[];
    constexpr int NKB=4*KBW, C=KBW/4;
    constexpr int RED= SEC? 2048 : 0;
    uint2* Wpk=(uint2*)sm;
    float* stgb=sm+NKB*512;
    const int tid=threadIdx.x, l=tid&31, w=tid>>5;
    const int wg=w>>2, wl=w&3, wm=wl>>1, wn=wl&1;
    const int g=l>>2, tg=l&3;
    const int wtid=tid&127;
    const int strip=blockIdx.x&31, bg=blockIdx.x>>5;
    const int barid=wg+1;
    float* stg=stgb+wg*6144;

    for(int e=tid;e<NKB*256;e+=512){
        int tg_=e&3, ci=(e>>2)&63, kb=e>>8;
        int nt=ci>>4, wn_=(ci>>3)&1, gg=ci&7;
        int gcol=nt*HID+strip*16+wn_*8+gg;
        const float* W=W0; int kk=kb;
        if(SEC&&kb>=32){ W=W1; kk=kb-32; }
        int k0=kk*16+tg_*2;
        uint2 v;
        v.x=pk2(W[(size_t)k0*G4+gcol],     W[(size_t)(k0+1)*G4+gcol]);
        v.y=pk2(W[(size_t)(k0+8)*G4+gcol], W[(size_t)(k0+9)*G4+gcol]);
        Wpk[e]=v;
    }
    __syncthreads();

    float cst[2][4];
#pragma unroll
    for(int m=0;m<2;m++) for(int q=0;q<4;q++) cst[m][q]=0.f;
    float xzp[2][4][4];
    float bz[4][2];

    auto pfxz=[&](int tt){
        const float* xr=xz+(size_t)tt*BAT*G4;
#pragma unroll
        for(int mt=0;mt<2;mt++)
#pragma unroll
            for(int nt=0;nt<4;nt++){
                int b=bg*64+wm*32+mt*16+g;
                int cc=nt*HID+strip*16+wn*8+tg*2;
                float2 v0=*(const float2*)&xr[(size_t)b*G4+cc];
                float2 v1=*(const float2*)&xr[(size_t)(b+8)*G4+cc];
                xzp[mt][nt][0]=v0.x; xzp[mt][nt][1]=v0.y;
                xzp[mt][nt][2]=v1.x; xzp[mt][nt][3]=v1.y;
            }
    };
    if(wg==1){
        if(!SEC) pfxz(0);
        else {
#pragma unroll
            for(int nt=0;nt<4;nt++){
                int cc=nt*HID+strip*16+wn*8+tg*2;
                bz[nt][0]=bias[cc]; bz[nt][1]=bias[cc+1];
            }
        }
    }

    auto kbgOf=[&](int c,int kbl){
        int x=c*4+kbl;
        return SEC? ((x<8)? wg*8+x : 32+wg*8+(x-8)) : wg*8+x;
    };
    auto issueA=[&](int t,int c){
        float* dst=stg+(c%3)*2048;
        const unsigned* hb1=g_Hb1[t&1];
        const unsigned* hb2=g_Hb2[t&1];
#pragma unroll
        for(int q=0;q<4;q++){
            int e=wtid+128*q;
            int kbl=e>>7, rem=e&127, r=rem>>1, hf=rem&1;
            int kbg=kbgOf(c,kbl);
            const unsigned* src; size_t off;
            if(!SEC){ src=hb1; off=(size_t)kbg*BAT; }
            else if(kbg<32){ src=g_H1p; off=((size_t)t*32+kbg)*BAT; }
            else { src=hb2; off=(size_t)(kbg-32)*BAT; }
            cp16(su32(dst+(kbl*64+r)*8+hf*4), src+(off+bg*64+r)*8+hf*4);
        }
    };
    auto mmaC=[&](float acc[2][4][4],int c){
        const unsigned* Au=(const unsigned*)(stg+(c%3)*2048);
#pragma unroll
        for(int kbl=0;kbl<4;kbl++){
            int kbg=kbgOf(c,kbl);
            uint2 x0[2],x1[2];
#pragma unroll
            for(int mt=0;mt<2;mt++){
                int r=wm*32+mt*16+g;
                x0[mt]=*(const uint2*)&Au[(kbl*64+r)*8+tg*2];
                x1[mt]=*(const uint2*)&Au[(kbl*64+r+8)*8+tg*2];
            }
#pragma unroll
            for(int nt=0;nt<4;nt++){
                uint2 bv=Wpk[(kbg*64+nt*16+wn*8+g)*4+tg];
                mma16(acc[0][nt],x0[0].x,x1[0].x,x0[0].y,x1[0].y,bv.x,bv.y);
                mma16(acc[1][nt],x0[1].x,x1[1].x,x0[1].y,x1[1].y,bv.x,bv.y);
            }
        }
    };

    for(int t=0;t<TST;t++){
        // SEC: pre-issue h1 chunk 0 (buf0, outside red region) to hide under poll
        if(SEC){ issueA(t,0); cpc(); }
        if(t>0){
            if(tid<32){
                const volatile unsigned* f=&g_sync[(bg*32+tid)*32];
                unsigned tgt=base+(unsigned)t;
                while(*f<tgt){}
            }
            __threadfence(); __syncthreads();
        }
        if(SEC){ issueA(t,1); cpc(); }
        else { issueA(t,0); cpc(); issueA(t,1); cpc(); }

        float acc[2][4][4];
        if(wg==1){
            if(!SEC){
#pragma unroll
                for(int mt=0;mt<2;mt++) for(int nt=0;nt<4;nt++)
                    for(int q=0;q<4;q++) acc[mt][nt][q]=xzp[mt][nt][q];
                if(t+1<TST) pfxz(t+1);
            } else {
#pragma unroll
                for(int mt=0;mt<2;mt++) for(int nt=0;nt<4;nt++){
                    acc[mt][nt][0]=bz[nt][0]; acc[mt][nt][1]=bz[nt][1];
                    acc[mt][nt][2]=bz[nt][0]; acc[mt][nt][3]=bz[nt][1];
                }
            }
        } else {
#pragma unroll
            for(int m=0;m<2;m++) for(int n=0;n<4;n++)
                for(int q=0;q<4;q++) acc[m][n][q]=0.f;
        }

        for(int c=0;c<C;c++){
            if(c<C-1) cpw<1>(); else cpw<0>();
            barwg(barid);
            if(c+2<C){ issueA(t,c+2); cpc(); }
            mmaC(acc,c);
        }
        barwg(barid);

        if(wg!=0){
            float4* redw=(float4*)(stg+RED);   // 4096 floats = 1024 float4
#pragma unroll
            for(int mt=0;mt<2;mt++)
#pragma unroll
                for(int nt=0;nt<4;nt++){
                    int jj=mt*4+nt;
                    float4 v={acc[mt][nt][0],acc[mt][nt][1],
                              acc[mt][nt][2],acc[mt][nt][3]};
                    redw[wtid*8+((jj+wtid)&7)]=v;
                }
        }
        __syncthreads();
        if(wg==0){
            unsigned* hn = SEC? g_Hb2[(t&1)^1] : g_Hb1[(t&1)^1];
#pragma unroll
            for(int mt=0;mt<2;mt++){
                float hq[2][2];
#pragma unroll
                for(int nt=0;nt<4;nt++){
                    int jj=mt*4+nt;
#pragma unroll
                    for(int ww=1;ww<4;ww++){
                        const float4* redw=(const float4*)(stgb+ww*6144+RED);
                        float4 v=redw[wtid*8+((jj+wtid)&7)];
                        acc[mt][nt][0]+=v.x; acc[mt][nt][1]+=v.y;
                        acc[mt][nt][2]+=v.z; acc[mt][nt][3]+=v.w;
                    }
                }
#pragma unroll
                for(int q=0;q<4;q++){
                    float ig=siga(acc[mt][0][q]);
                    float fg=siga(acc[mt][1][q]);
                    float gv=tanha(acc[mt][2][q]);
                    float og=siga(acc[mt][3][q]);
                    float cc_=fg*cst[mt][q]+ig*gv;
                    cst[mt][q]=cc_;
                    hq[q>>1][q&1]=og*tanha(cc_);
                }
#pragma unroll
                for(int p=0;p<2;p++){
                    int b=bg*64+wm*32+mt*16+p*8+g;
                    int U0=strip*16+wn*8+tg*2;
                    unsigned pv=pk2(hq[p][0],hq[p][1]);
                    if(SEC) *(unsigned*)&g_H2[((size_t)t*BAT+b)*HID+U0]=pv;
                    else g_H1p[(((size_t)t*32+strip)*BAT+b)*8+tg*2+wn]=pv;
                    hn[((size_t)strip*BAT+b)*8+tg*2+wn]=pv;
                }
            }
            barwg(1);
            if(tid==0){
                __threadfence();
                g_sync[(bg*32+strip)*32]=base+(unsigned)(t+1);
            }
        }
    }
}

// ---------------- heads ----------------
__global__ __launch_bounds__(256) void head_k(const __nv_bfloat16* __restrict__ h,
        const float* __restrict__ Wmu, const float* __restrict__ bmu,
        const float* __restrict__ Wsig, const float* __restrict__ bsig,
        float* __restrict__ out){
    int w=threadIdx.x>>5, l=threadIdx.x&31;
    int r=blockIdx.x*8+w;
    const __nv_bfloat16* hr=h+(size_t)r*HID;
    float smu=0.f, ssg=0.f;
    for(int k=l;k<HID;k+=32){
        float hv=__bfloat162float(hr[k]);
        smu+=hv*Wmu[k]; ssg+=hv*Wsig[k];
    }
#pragma unroll
    for(int o=16;o;o>>=1){
        smu+=__shfl_xor_sync(0xFFFFFFFFu,smu,o);
        ssg+=__shfl_xor_sync(0xFFFFFFFFu,ssg,o);
    }
    if(l==0){
        int t=r>>8, b=r&255;
        out[b*TST+t]=smu+bmu[0];
        float x=ssg+bsig[0];
        out[RWS+b*TST+t]=(x>20.f)? x : log1pf(__expf(x));
    }
}

extern "C" void kernel_launch(void* const* d_in, const int* in_sizes, int n_in,
                              void* d_out, int out_size){
    const float* xc  =(const float*)d_in[0];
    const int*   c0  =(const int*  )d_in[1];
    const int*   c1  =(const int*  )d_in[2];
    const float* e0  =(const float*)d_in[3];
    const float* e1  =(const float*)d_in[4];
    const float* Wk1 =(const float*)d_in[5];
    const float* Wr1 =(const float*)d_in[6];
    const float* b1  =(const float*)d_in[7];
    const float* Wk2 =(const float*)d_in[8];
    const float* Wr2 =(const float*)d_in[9];
    const float* b2  =(const float*)d_in[10];
    const float* Wmu =(const float*)d_in[11];
    const float* bmu =(const float*)d_in[12];
    const float* Wsig=(const float*)d_in[13];
    const float* bsig=(const float*)d_in[14];
    float* out=(float*)d_out;

    cudaFuncSetAttribute(lstm_t<8,false>,
        cudaFuncAttributeMaxDynamicSharedMemorySize, 163840);
    cudaFuncSetAttribute(lstm_t<16,true>,
        cudaFuncAttributeMaxDynamicSharedMemorySize, 229376);
    cudaFuncSetAttribute(gemm64, cudaFuncAttributeMaxDynamicSharedMemorySize, 36864);

    void *pX,*pXZ,*pH2,*pW1;
    cudaGetSymbolAddress(&pX,  g_X);
    cudaGetSymbolAddress(&pXZ, g_XZ);
    cudaGetSymbolAddress(&pH2, g_H2);
    cudaGetSymbolAddress(&pW1, g_Wk1p);

    prep_k<<<3072,256>>>(xc,c0,c1,e0,e1,Wk1);
    zero_k<<<1024,256>>>();
    gemm64<<<dim3(32,RWS/64),128,36864>>>((const __nv_bfloat16*)pX,
        (const unsigned*)pW1,b1,(float*)pXZ,64);
    lstm_t<8,false><<<128,512,163840>>>((const float*)pXZ,Wr1,Wr1,b1,0u);
    lstm_t<16,true><<<128,512,229376>>>((const float*)pXZ,Wk2,Wr2,b2,192u);
    head_k<<<RWS/8,256>>>((const __nv_bfloat16*)pH2,Wmu,bmu,Wsig,bsig,out);
    rst_k<<<1,128>>>();
}